// round 2
// baseline (speedup 1.0000x reference)
#include <cuda_runtime.h>

#define BATCH 8
#define LEN   2048
#define EMB   512
#define NQ    8
#define IT    4      // i-rows per attn block

// scratch for rot = x @ rotation : (8, 2048, 8) fp32 = 512 KB (L2-resident)
__device__ float g_rot[BATCH * LEN * NQ];

// ---------------- packed f32x2 helpers (Blackwell FFMA2 path) ----------------
__device__ __forceinline__ unsigned long long pack2(float lo, float hi) {
    unsigned long long d;
    asm("mov.b64 %0, {%1, %2};" : "=l"(d) : "f"(lo), "f"(hi));
    return d;
}
__device__ __forceinline__ void unpack2(unsigned long long d, float& lo, float& hi) {
    asm("mov.b64 {%0, %1}, %2;" : "=f"(lo), "=f"(hi) : "l"(d));
}
__device__ __forceinline__ unsigned long long fma2(unsigned long long a,
                                                   unsigned long long b,
                                                   unsigned long long c) {
    unsigned long long d;
    asm("fma.rn.f32x2 %0, %1, %2, %3;" : "=l"(d) : "l"(a), "l"(b), "l"(c));
    return d;
}
__device__ __forceinline__ float tanh_fast(float x) {
    float y;
    asm("tanh.approx.f32 %0, %1;" : "=f"(y) : "f"(x));
    return y;
}

// ---------------------------------------------------------------------------
// Kernel 1: rot[b,l,q] = sum_e x[b,l,e] * rotation[e,q]
// Block = 256 (8 warps), warp computes 4 rows with float4 loads (high MLP).
// Full butterfly reduce -> every lane holds every sum -> lane L stores the
// (row = L>>3, q = L&7) element: one coalesced 128B store per warp.
// ---------------------------------------------------------------------------
__global__ __launch_bounds__(256) void rot_kernel(const float* __restrict__ x,
                                                  const float* __restrict__ rotation)
{
    __shared__ float4 srotT4[NQ][EMB / 4];   // transposed rotation, 16 KB
    const int tid = threadIdx.x;

    float* srot = reinterpret_cast<float*>(srotT4);
    for (int idx = tid; idx < EMB * NQ; idx += 256) {
        int e = idx >> 3;
        int q = idx & 7;
        srot[q * EMB + e] = rotation[idx];
    }
    __syncthreads();

    const int warp = tid >> 5;
    const int lane = tid & 31;
    const int row0 = (blockIdx.x * 8 + warp) * 4;

    float acc[4][NQ];
#pragma unroll
    for (int r = 0; r < 4; r++)
#pragma unroll
        for (int q = 0; q < NQ; q++) acc[r][q] = 0.0f;

#pragma unroll
    for (int k = 0; k < 4; k++) {
        const int e4 = k * 32 + lane;   // float4 index within the row
        float4 xv[4];
#pragma unroll
        for (int r = 0; r < 4; r++)
            xv[r] = reinterpret_cast<const float4*>(x + (size_t)(row0 + r) * EMB)[e4];
#pragma unroll
        for (int q = 0; q < NQ; q++) {
            const float4 rq = srotT4[q][e4];
#pragma unroll
            for (int r = 0; r < 4; r++) {
                acc[r][q] = fmaf(xv[r].x, rq.x, acc[r][q]);
                acc[r][q] = fmaf(xv[r].y, rq.y, acc[r][q]);
                acc[r][q] = fmaf(xv[r].z, rq.z, acc[r][q]);
                acc[r][q] = fmaf(xv[r].w, rq.w, acc[r][q]);
            }
        }
    }

    // butterfly all-reduce: every lane ends with the full sum for all 32 (r,q)
#pragma unroll
    for (int r = 0; r < 4; r++)
#pragma unroll
        for (int q = 0; q < NQ; q++) {
#pragma unroll
            for (int off = 16; off > 0; off >>= 1)
                acc[r][q] += __shfl_xor_sync(0xffffffffu, acc[r][q], off);
        }

    // lane L owns element (r = L>>3, q = L&7) -> one coalesced 128B store/warp
    float outv = 0.0f;
#pragma unroll
    for (int r = 0; r < 4; r++)
#pragma unroll
        for (int q = 0; q < NQ; q++)
            if (lane == r * 8 + q) outv = acc[r][q];
    g_rot[(size_t)row0 * NQ + lane] = outv;
}

// ---------------------------------------------------------------------------
// Kernel 2: scores[b,i,j] = sigmoid(rot_i . rot_j) / row_sum
//   sigmoid(s) = 0.5 + 0.5*tanh(0.5*s); the 0.5 is folded into qi (pre-scaled).
//   row_sum    = 1024 + 0.5 * sum_j tanh(0.5*s)
//   out        = fmaf(t, h, h) with h = 0.5 / row_sum
// Block = 512 threads, IT=4 i-rows per block (grid 512x8), 2 blocks/SM.
// Thread t owns j in [4t, 4t+4); j-rows packed pairwise for fma.rn.f32x2.
// ---------------------------------------------------------------------------
__global__ __launch_bounds__(512, 2) void attn_kernel(float* __restrict__ out)
{
    const int b    = blockIdx.y;
    const int i0   = blockIdx.x * IT;
    const int tid  = threadIdx.x;
    const int warp = tid >> 5;
    const int lane = tid & 31;

    __shared__ unsigned long long s_qq[IT * NQ];  // 0.5*qi, duplicated in both halves
    __shared__ float s_part[IT][16];
    __shared__ float s_h[IT];

    if (tid < IT * NQ) {
        const float v = 0.5f * g_rot[((size_t)b * LEN + i0) * NQ + tid];
        s_qq[tid] = pack2(v, v);
    }

    // this thread's 4 j-rows, packed pairwise: v01 = {row j0, row j1}, v23 = {j2, j3}
    const float4* rj = reinterpret_cast<const float4*>(
        &g_rot[((size_t)b * LEN + tid * 4) * NQ]);
    unsigned long long v01[NQ], v23[NQ];
    {
        const float4 a0 = rj[0], a1 = rj[1], c0 = rj[2], c1 = rj[3];
        v01[0] = pack2(a0.x, c0.x); v01[1] = pack2(a0.y, c0.y);
        v01[2] = pack2(a0.z, c0.z); v01[3] = pack2(a0.w, c0.w);
        v01[4] = pack2(a1.x, c1.x); v01[5] = pack2(a1.y, c1.y);
        v01[6] = pack2(a1.z, c1.z); v01[7] = pack2(a1.w, c1.w);
    }
    {
        const float4 a0 = rj[4], a1 = rj[5], c0 = rj[6], c1 = rj[7];
        v23[0] = pack2(a0.x, c0.x); v23[1] = pack2(a0.y, c0.y);
        v23[2] = pack2(a0.z, c0.z); v23[3] = pack2(a0.w, c0.w);
        v23[4] = pack2(a1.x, c1.x); v23[5] = pack2(a1.y, c1.y);
        v23[6] = pack2(a1.z, c1.z); v23[7] = pack2(a1.w, c1.w);
    }

    __syncthreads();

    float t[IT][4];
    float psum[IT];

#pragma unroll
    for (int i = 0; i < IT; i++) {
        unsigned long long acc01 = 0ull, acc23 = 0ull;   // {0.0f, 0.0f}
#pragma unroll
        for (int q = 0; q < NQ; q++) {
            const unsigned long long qq = s_qq[i * NQ + q];   // LDS.64 broadcast
            acc01 = fma2(v01[q], qq, acc01);
            acc23 = fma2(v23[q], qq, acc23);
        }
        float s0, s1, s2, s3;
        unpack2(acc01, s0, s1);
        unpack2(acc23, s2, s3);
        t[i][0] = tanh_fast(s0);
        t[i][1] = tanh_fast(s1);
        t[i][2] = tanh_fast(s2);
        t[i][3] = tanh_fast(s3);
        psum[i] = (t[i][0] + t[i][1]) + (t[i][2] + t[i][3]);
    }

#pragma unroll
    for (int i = 0; i < IT; i++) {
        float p = psum[i];
#pragma unroll
        for (int off = 16; off > 0; off >>= 1)
            p += __shfl_xor_sync(0xffffffffu, p, off);
        if (lane == 0) s_part[i][warp] = p;
    }

    __syncthreads();

    if (tid < IT) {
        float s = 0.0f;
#pragma unroll
        for (int w = 0; w < 16; w++) s += s_part[tid][w];
        // h = 0.5 / (1024 + 0.5*sum_t)
        s_h[tid] = __fdividef(0.5f, fmaf(0.5f, s, 1024.0f));
    }
    __syncthreads();

#pragma unroll
    for (int i = 0; i < IT; i++) {
        const float h = s_h[i];
        float4 o;
        o.x = fmaf(t[i][0], h, h);
        o.y = fmaf(t[i][1], h, h);
        o.z = fmaf(t[i][2], h, h);
        o.w = fmaf(t[i][3], h, h);
        reinterpret_cast<float4*>(
            &out[((size_t)(b * LEN + i0 + i)) * LEN + tid * 4])[0] = o;
    }
}

extern "C" void kernel_launch(void* const* d_in, const int* in_sizes, int n_in,
                              void* d_out, int out_size)
{
    const float* x        = (const float*)d_in[0];   // (8, 2048, 512)
    const float* rotation = (const float*)d_in[1];   // (512, 8)
    float* out = (float*)d_out;                      // (8, 2048, 2048)

    rot_kernel<<<512, 256>>>(x, rotation);

    dim3 grid(LEN / IT, BATCH);                      // (512, 8)
    attn_kernel<<<grid, 512>>>(out);
}

// round 3
// speedup vs baseline: 1.2487x; 1.2487x over previous
#include <cuda_runtime.h>

#define BATCH 8
#define LEN   2048
#define EMB   512
#define NQ    8
#define IT    8      // i-rows per attn block

// scratch for rot = x @ rotation : (8, 2048, 8) fp32 = 512 KB (L2-resident)
__device__ float g_rot[BATCH * LEN * NQ];

// ---------------- packed f32x2 helpers (Blackwell FFMA2 path) ----------------
__device__ __forceinline__ unsigned long long pack2(float lo, float hi) {
    unsigned long long d;
    asm("mov.b64 %0, {%1, %2};" : "=l"(d) : "f"(lo), "f"(hi));
    return d;
}
__device__ __forceinline__ void unpack2(unsigned long long d, float& lo, float& hi) {
    asm("mov.b64 {%0, %1}, %2;" : "=f"(lo), "=f"(hi) : "l"(d));
}
__device__ __forceinline__ unsigned long long fma2(unsigned long long a,
                                                   unsigned long long b,
                                                   unsigned long long c) {
    unsigned long long d;
    asm("fma.rn.f32x2 %0, %1, %2, %3;" : "=l"(d) : "l"(a), "l"(b), "l"(c));
    return d;
}
__device__ __forceinline__ unsigned long long add2(unsigned long long a,
                                                   unsigned long long b) {
    unsigned long long d;
    asm("add.rn.f32x2 %0, %1, %2;" : "=l"(d) : "l"(a), "l"(b));
    return d;
}
__device__ __forceinline__ float tanh_fast(float x) {
    float y;
    asm("tanh.approx.f32 %0, %1;" : "=f"(y) : "f"(x));
    return y;
}

// ---------------------------------------------------------------------------
// Kernel 1: rot[b,l,q] = sum_e x[b,l,e] * rotation[e,q]
// 1024 blocks x 256 threads. Each warp computes 2 rows; all 8 row-loads
// (LDG.128) issued up-front for MLP=8. Butterfly all-reduce (16 independent
// chains), lanes 0..15 store the 2x8 result block coalesced.
// ---------------------------------------------------------------------------
__global__ __launch_bounds__(256) void rot_kernel(const float* __restrict__ x,
                                                  const float* __restrict__ rotation)
{
    __shared__ float4 srotT4[NQ][EMB / 4];   // transposed rotation, 16 KB
    const int tid = threadIdx.x;

    float* srot = reinterpret_cast<float*>(srotT4);
    for (int idx = tid; idx < EMB * NQ; idx += 256) {
        int e = idx >> 3;
        int q = idx & 7;
        srot[q * EMB + e] = rotation[idx];
    }
    __syncthreads();

    const int warp = tid >> 5;
    const int lane = tid & 31;
    const int row0 = (blockIdx.x * 8 + warp) * 2;   // 2 rows per warp

    // issue all 8 global loads first (2 rows x 4 chunks), MLP = 8
    float4 xv[2][4];
#pragma unroll
    for (int r = 0; r < 2; r++)
#pragma unroll
        for (int k = 0; k < 4; k++)
            xv[r][k] = reinterpret_cast<const float4*>(
                x + (size_t)(row0 + r) * EMB)[k * 32 + lane];

    float acc[2][NQ];
#pragma unroll
    for (int r = 0; r < 2; r++)
#pragma unroll
        for (int q = 0; q < NQ; q++) acc[r][q] = 0.0f;

#pragma unroll
    for (int k = 0; k < 4; k++) {
#pragma unroll
        for (int q = 0; q < NQ; q++) {
            const float4 rq = srotT4[q][k * 32 + lane];
#pragma unroll
            for (int r = 0; r < 2; r++) {
                acc[r][q] = fmaf(xv[r][k].x, rq.x, acc[r][q]);
                acc[r][q] = fmaf(xv[r][k].y, rq.y, acc[r][q]);
                acc[r][q] = fmaf(xv[r][k].z, rq.z, acc[r][q]);
                acc[r][q] = fmaf(xv[r][k].w, rq.w, acc[r][q]);
            }
        }
    }

    // butterfly all-reduce: 16 independent 5-stage chains, fully interleaved
#pragma unroll
    for (int off = 16; off > 0; off >>= 1) {
#pragma unroll
        for (int r = 0; r < 2; r++)
#pragma unroll
            for (int q = 0; q < NQ; q++)
                acc[r][q] += __shfl_xor_sync(0xffffffffu, acc[r][q], off);
    }

    // lane L (<16) owns element (r = L>>3, q = L&7): one coalesced 64B store
    if (lane < 16) {
        float outv = 0.0f;
#pragma unroll
        for (int r = 0; r < 2; r++)
#pragma unroll
            for (int q = 0; q < NQ; q++)
                if (lane == r * 8 + q) outv = acc[r][q];
        g_rot[(size_t)row0 * NQ + lane] = outv;
    }
}

// ---------------------------------------------------------------------------
// Kernel 2: scores[b,i,j] = sigmoid(rot_i . rot_j) / row_sum
//   sigmoid(s) = 0.5 + 0.5*tanh(0.5*s)   (0.5 folded into qi)
//   row_sum    = 1024 + 0.5*sum_j tanh   ->  out = fmaf(t, h, h), h = 0.5/row_sum
// Block = 1024 threads (32 warps), IT=8 i-rows, grid (256, 8) = 2048 blocks.
// Thread t owns j in {2t, 2t+1}; the 2 j-rows are packed element-wise for
// fma.rn.f32x2. All row reductions hoisted after the i-loop, interleaved.
// ---------------------------------------------------------------------------
__global__ __launch_bounds__(1024, 1) void attn_kernel(float* __restrict__ out)
{
    const int b    = blockIdx.y;
    const int i0   = blockIdx.x * IT;
    const int tid  = threadIdx.x;
    const int warp = tid >> 5;
    const int lane = tid & 31;

    __shared__ unsigned long long s_qq[IT * NQ];  // 0.5*qi, duplicated halves
    __shared__ float s_part[IT][32];
    __shared__ float s_h[IT];

    if (tid < IT * NQ) {
        const float v = 0.5f * g_rot[((size_t)b * LEN + i0) * NQ + tid];
        s_qq[tid] = pack2(v, v);
    }

    // this thread's 2 j-rows (64B contiguous), packed element-wise:
    // vq[q] = { rowA[q], rowB[q] }
    const float4* rj = reinterpret_cast<const float4*>(
        &g_rot[((size_t)b * LEN + tid * 2) * NQ]);
    const float4 a0 = rj[0], a1 = rj[1], b0 = rj[2], b1 = rj[3];
    unsigned long long vq[NQ];
    vq[0] = pack2(a0.x, b0.x); vq[1] = pack2(a0.y, b0.y);
    vq[2] = pack2(a0.z, b0.z); vq[3] = pack2(a0.w, b0.w);
    vq[4] = pack2(a1.x, b1.x); vq[5] = pack2(a1.y, b1.y);
    vq[6] = pack2(a1.z, b1.z); vq[7] = pack2(a1.w, b1.w);

    __syncthreads();

    float tA[IT], tB[IT], psum[IT];

#pragma unroll
    for (int i = 0; i < IT; i++) {
        // two independent 4-deep FFMA2 chains
        unsigned long long c0 = 0ull, c1 = 0ull;
#pragma unroll
        for (int q = 0; q < 4; q++) {
            c0 = fma2(vq[q],     s_qq[i * NQ + q],     c0);
            c1 = fma2(vq[q + 4], s_qq[i * NQ + q + 4], c1);
        }
        const unsigned long long acc = add2(c0, c1);
        float sA, sB;
        unpack2(acc, sA, sB);
        tA[i] = tanh_fast(sA);
        tB[i] = tanh_fast(sB);
        psum[i] = tA[i] + tB[i];
    }

    // warp-level reduction: 8 independent interleaved butterfly chains
#pragma unroll
    for (int off = 16; off > 0; off >>= 1) {
#pragma unroll
        for (int i = 0; i < IT; i++)
            psum[i] += __shfl_xor_sync(0xffffffffu, psum[i], off);
    }
    if (lane == 0) {
#pragma unroll
        for (int i = 0; i < IT; i++) s_part[i][warp] = psum[i];
    }

    __syncthreads();

    // second level: warp i (i<8) reduces row i's 32 partials
    if (warp < IT) {
        float p = s_part[warp][lane];
#pragma unroll
        for (int off = 16; off > 0; off >>= 1)
            p += __shfl_xor_sync(0xffffffffu, p, off);
        if (lane == 0)
            s_h[warp] = __fdividef(0.5f, fmaf(0.5f, p, 1024.0f));
    }
    __syncthreads();

#pragma unroll
    for (int i = 0; i < IT; i++) {
        const float h = s_h[i];
        float2 o;
        o.x = fmaf(tA[i], h, h);
        o.y = fmaf(tB[i], h, h);
        reinterpret_cast<float2*>(
            &out[((size_t)(b * LEN + i0 + i)) * LEN + tid * 2])[0] = o;
    }
}

extern "C" void kernel_launch(void* const* d_in, const int* in_sizes, int n_in,
                              void* d_out, int out_size)
{
    const float* x        = (const float*)d_in[0];   // (8, 2048, 512)
    const float* rotation = (const float*)d_in[1];   // (512, 8)
    float* out = (float*)d_out;                      // (8, 2048, 2048)

    rot_kernel<<<1024, 256>>>(x, rotation);

    dim3 grid(LEN / IT, BATCH);                      // (256, 8)
    attn_kernel<<<grid, 1024>>>(out);
}

// round 4
// speedup vs baseline: 1.3352x; 1.0693x over previous
#include <cuda_runtime.h>

#define BATCH 8
#define LEN   2048
#define EMB   512
#define NQ    8
#define IT    8      // i-rows per attn block

// scratch for rot = x @ rotation : (8, 2048, 8) fp32 = 512 KB (L2-resident)
__device__ float g_rot[BATCH * LEN * NQ];

// ---------------- packed f32x2 helpers (Blackwell FFMA2 path) ----------------
__device__ __forceinline__ unsigned long long pack2(float lo, float hi) {
    unsigned long long d;
    asm("mov.b64 %0, {%1, %2};" : "=l"(d) : "f"(lo), "f"(hi));
    return d;
}
__device__ __forceinline__ void unpack2(unsigned long long d, float& lo, float& hi) {
    asm("mov.b64 {%0, %1}, %2;" : "=f"(lo), "=f"(hi) : "l"(d));
}
__device__ __forceinline__ unsigned long long fma2(unsigned long long a,
                                                   unsigned long long b,
                                                   unsigned long long c) {
    unsigned long long d;
    asm("fma.rn.f32x2 %0, %1, %2, %3;" : "=l"(d) : "l"(a), "l"(b), "l"(c));
    return d;
}
__device__ __forceinline__ unsigned long long add2(unsigned long long a,
                                                   unsigned long long b) {
    unsigned long long d;
    asm("add.rn.f32x2 %0, %1, %2;" : "=l"(d) : "l"(a), "l"(b));
    return d;
}
__device__ __forceinline__ float tanh_fast(float x) {
    float y;
    asm("tanh.approx.f32 %0, %1;" : "=f"(y) : "f"(x));
    return y;
}

// ---------------------------------------------------------------------------
// Kernel 1: rot[b,l,q] = sum_e x[b,l,e] * rotation[e,q]
// 1024 blocks x 256 threads. Each warp computes 2 rows; all 8 row-loads
// (LDG.128) issued up-front (MLP=8). Swap-butterfly reduction: 16 accs
// reduced with 16 SHFL/thread (vs 80 for plain butterfly). Lane l (<16)
// ends owning element o = l (r = l>>3, q = l&7): coalesced 64B store.
// ---------------------------------------------------------------------------
__global__ __launch_bounds__(256) void rot_kernel(const float* __restrict__ x,
                                                  const float* __restrict__ rotation)
{
    __shared__ float4 srotT4[NQ][EMB / 4];   // transposed rotation, 16 KB
    const int tid = threadIdx.x;

    float* srot = reinterpret_cast<float*>(srotT4);
    for (int idx = tid; idx < EMB * NQ; idx += 256) {
        int e = idx >> 3;
        int q = idx & 7;
        srot[q * EMB + e] = rotation[idx];
    }
    __syncthreads();

    const int warp = tid >> 5;
    const int lane = tid & 31;
    const int row0 = (blockIdx.x * 8 + warp) * 2;   // 2 rows per warp

    // issue all 8 global loads first (2 rows x 4 chunks), MLP = 8
    float4 xv[2][4];
#pragma unroll
    for (int r = 0; r < 2; r++)
#pragma unroll
        for (int k = 0; k < 4; k++)
            xv[r][k] = reinterpret_cast<const float4*>(
                x + (size_t)(row0 + r) * EMB)[k * 32 + lane];

    float a[16];   // a[o], o = r*8+q
#pragma unroll
    for (int o = 0; o < 16; o++) a[o] = 0.0f;

#pragma unroll
    for (int k = 0; k < 4; k++) {
#pragma unroll
        for (int q = 0; q < NQ; q++) {
            const float4 rq = srotT4[q][k * 32 + lane];
#pragma unroll
            for (int r = 0; r < 2; r++) {
                float& acc = a[r * 8 + q];
                acc = fmaf(xv[r][k].x, rq.x, acc);
                acc = fmaf(xv[r][k].y, rq.y, acc);
                acc = fmaf(xv[r][k].z, rq.z, acc);
                acc = fmaf(xv[r][k].w, rq.w, acc);
            }
        }
    }

    // swap-butterfly reduce: stages off = 8,4,2,1 exchange complementary
    // halves; after them lane l holds acc[l&15] summed over its 16-lane group.
#pragma unroll
    for (int off = 8; off >= 1; off >>= 1) {
#pragma unroll
        for (int t = 0; t < 16; t += 1) { }   // (placeholder removed by compiler)
#pragma unroll
        for (int t = 0; t < 8; t++) {
            if (t < off) {
                const bool hi = (lane & off) != 0;
                const float give = hi ? a[t] : a[t + off];
                const float keep = hi ? a[t + off] : a[t];
                a[t] = keep + __shfl_xor_sync(0xffffffffu, give, off);
            }
        }
    }
    // final stage: combine the two 16-lane groups
    a[0] += __shfl_xor_sync(0xffffffffu, a[0], 16);

    if (lane < 16)
        g_rot[(size_t)row0 * NQ + lane] = a[0];
}

// ---------------------------------------------------------------------------
// Kernel 2: scores[b,i,j] = sigmoid(rot_i . rot_j) / row_sum
//   sigmoid(s) = 0.5 + 0.5*tanh(0.5*s)   (0.5 folded into qi)
//   row_sum    = 1024 + 0.5*sum_j tanh   ->  out = fmaf(t, h, h), h = 0.5/row_sum
// Block = 1024 threads, IT=8 i-rows, grid (256, 8). Thread t owns j = {2t,2t+1}
// packed as f32x2. Broadcast qi loaded as LDS.128 (4 per i, was 8 LDS.64).
// Row-sum reduction: swap-butterfly, 9 SHFL/thread (was 40).
// ---------------------------------------------------------------------------
__global__ __launch_bounds__(1024, 1) void attn_kernel(float* __restrict__ out)
{
    const int b    = blockIdx.y;
    const int i0   = blockIdx.x * IT;
    const int tid  = threadIdx.x;
    const int warp = tid >> 5;
    const int lane = tid & 31;

    __shared__ ulonglong2 s_qq2[IT * 4];   // [i*4+p] = {qq[2p], qq[2p+1]}, qq=0.5*qi dup
    __shared__ float s_part[IT][32];
    __shared__ float s_h[IT];

    if (tid < IT * NQ) {
        const float v = 0.5f * g_rot[((size_t)b * LEN + i0) * NQ + tid];
        reinterpret_cast<unsigned long long*>(s_qq2)[tid] = pack2(v, v);
    }

    // this thread's 2 j-rows (64B contiguous), packed element-wise:
    // vq[q] = { rowA[q], rowB[q] }
    const float4* rj = reinterpret_cast<const float4*>(
        &g_rot[((size_t)b * LEN + tid * 2) * NQ]);
    const float4 a0 = rj[0], a1 = rj[1], b0 = rj[2], b1 = rj[3];
    unsigned long long vq[NQ];
    vq[0] = pack2(a0.x, b0.x); vq[1] = pack2(a0.y, b0.y);
    vq[2] = pack2(a0.z, b0.z); vq[3] = pack2(a0.w, b0.w);
    vq[4] = pack2(a1.x, b1.x); vq[5] = pack2(a1.y, b1.y);
    vq[6] = pack2(a1.z, b1.z); vq[7] = pack2(a1.w, b1.w);

    __syncthreads();

    float tA[IT], tB[IT], a[IT];

#pragma unroll
    for (int i = 0; i < IT; i++) {
        // 4x LDS.128 fetch the 8 broadcast qq values for row i
        const ulonglong2 p0 = s_qq2[i * 4 + 0];
        const ulonglong2 p1 = s_qq2[i * 4 + 1];
        const ulonglong2 p2 = s_qq2[i * 4 + 2];
        const ulonglong2 p3 = s_qq2[i * 4 + 3];
        // two independent 4-deep FFMA2 chains
        unsigned long long c0 = 0ull, c1 = 0ull;
        c0 = fma2(vq[0], p0.x, c0);  c1 = fma2(vq[4], p2.x, c1);
        c0 = fma2(vq[1], p0.y, c0);  c1 = fma2(vq[5], p2.y, c1);
        c0 = fma2(vq[2], p1.x, c0);  c1 = fma2(vq[6], p3.x, c1);
        c0 = fma2(vq[3], p1.y, c0);  c1 = fma2(vq[7], p3.y, c1);
        const unsigned long long acc = add2(c0, c1);
        float sA, sB;
        unpack2(acc, sA, sB);
        tA[i] = tanh_fast(sA);
        tB[i] = tanh_fast(sB);
        a[i] = tA[i] + tB[i];
    }

    // swap-butterfly warp reduce of the 8 row partials: stages 4,2,1 then 8,16.
    // After: every lane holds this warp's partial sum for row (lane & 7).
#pragma unroll
    for (int off = 4; off >= 1; off >>= 1) {
#pragma unroll
        for (int t = 0; t < 4; t++) {
            if (t < off) {
                const bool hi = (lane & off) != 0;
                const float give = hi ? a[t] : a[t + off];
                const float keep = hi ? a[t + off] : a[t];
                a[t] = keep + __shfl_xor_sync(0xffffffffu, give, off);
            }
        }
    }
    a[0] += __shfl_xor_sync(0xffffffffu, a[0], 8);
    a[0] += __shfl_xor_sync(0xffffffffu, a[0], 16);

    if (lane < IT)
        s_part[lane][warp] = a[0];

    __syncthreads();

    // second level: warp i (<8) reduces row i's 32 warp-partials
    if (warp < IT) {
        float p = s_part[warp][lane];
#pragma unroll
        for (int off = 16; off > 0; off >>= 1)
            p += __shfl_xor_sync(0xffffffffu, p, off);
        if (lane == 0)
            s_h[warp] = __fdividef(0.5f, fmaf(0.5f, p, 1024.0f));
    }
    __syncthreads();

    float* obase = out + ((size_t)(b * LEN + i0)) * LEN + tid * 2;
#pragma unroll
    for (int i = 0; i < IT; i++) {
        const float h = s_h[i];
        float2 o;
        o.x = fmaf(tA[i], h, h);
        o.y = fmaf(tB[i], h, h);
        *reinterpret_cast<float2*>(obase) = o;
        obase += LEN;
    }
}

extern "C" void kernel_launch(void* const* d_in, const int* in_sizes, int n_in,
                              void* d_out, int out_size)
{
    const float* x        = (const float*)d_in[0];   // (8, 2048, 512)
    const float* rotation = (const float*)d_in[1];   // (512, 8)
    float* out = (float*)d_out;                      // (8, 2048, 2048)

    rot_kernel<<<1024, 256>>>(x, rotation);

    dim3 grid(LEN / IT, BATCH);                      // (256, 8)
    attn_kernel<<<grid, 1024>>>(out);
}

// round 5
// speedup vs baseline: 1.5577x; 1.1666x over previous
#include <cuda_runtime.h>

#define BATCH 8
#define LEN   2048
#define EMB   512
#define NQ    8
#define IT    8      // i-rows per attn block

// scratch for rot = x @ rotation : (8, 2048, 8) fp32 = 512 KB (L2-resident)
__device__ float g_rot[BATCH * LEN * NQ];

__device__ __forceinline__ float tanh_fast(float x) {
    float y;
    asm("tanh.approx.f32 %0, %1;" : "=f"(y) : "f"(x));
    return y;
}

// ---------------------------------------------------------------------------
// Kernel 1: rot[b,l,q] = sum_e x[b,l,e] * rotation[e,q]
// 1024 blocks x 256 threads. Each warp computes 2 rows; all 8 row-loads
// (LDG.128) issued up-front (MLP=8). Swap-butterfly reduction (16 SHFL),
// lanes 0..15 store the 2x8 result block coalesced.
// ---------------------------------------------------------------------------
__global__ __launch_bounds__(256) void rot_kernel(const float* __restrict__ x,
                                                  const float* __restrict__ rotation)
{
    __shared__ float4 srotT4[NQ][EMB / 4];   // transposed rotation, 16 KB
    const int tid = threadIdx.x;

    float* srot = reinterpret_cast<float*>(srotT4);
    for (int idx = tid; idx < EMB * NQ; idx += 256) {
        int e = idx >> 3;
        int q = idx & 7;
        srot[q * EMB + e] = rotation[idx];
    }
    __syncthreads();

    const int warp = tid >> 5;
    const int lane = tid & 31;
    const int row0 = (blockIdx.x * 8 + warp) * 2;   // 2 rows per warp

    // issue all 8 global loads first (2 rows x 4 chunks), MLP = 8
    float4 xv[2][4];
#pragma unroll
    for (int r = 0; r < 2; r++)
#pragma unroll
        for (int k = 0; k < 4; k++)
            xv[r][k] = reinterpret_cast<const float4*>(
                x + (size_t)(row0 + r) * EMB)[k * 32 + lane];

    float a[16];   // a[o], o = r*8+q
#pragma unroll
    for (int o = 0; o < 16; o++) a[o] = 0.0f;

#pragma unroll
    for (int k = 0; k < 4; k++) {
#pragma unroll
        for (int q = 0; q < NQ; q++) {
            const float4 rq = srotT4[q][k * 32 + lane];
#pragma unroll
            for (int r = 0; r < 2; r++) {
                float& acc = a[r * 8 + q];
                acc = fmaf(xv[r][k].x, rq.x, acc);
                acc = fmaf(xv[r][k].y, rq.y, acc);
                acc = fmaf(xv[r][k].z, rq.z, acc);
                acc = fmaf(xv[r][k].w, rq.w, acc);
            }
        }
    }

    // swap-butterfly reduce: stages off = 8,4,2,1; after them lane l holds
    // acc[l&15] summed over its 16-lane group; one extra stage merges groups.
#pragma unroll
    for (int off = 8; off >= 1; off >>= 1) {
#pragma unroll
        for (int t = 0; t < 8; t++) {
            if (t < off) {
                const bool hi = (lane & off) != 0;
                const float give = hi ? a[t] : a[t + off];
                const float keep = hi ? a[t + off] : a[t];
                a[t] = keep + __shfl_xor_sync(0xffffffffu, give, off);
            }
        }
    }
    a[0] += __shfl_xor_sync(0xffffffffu, a[0], 16);

    if (lane < 16)
        g_rot[(size_t)row0 * NQ + lane] = a[0];
}

// ---------------------------------------------------------------------------
// Kernel 2: scores[b,i,j] = sigmoid(rot_i . rot_j) / row_sum
//   sigmoid(s) = 0.5 + 0.5*tanh(0.5*s)   (0.5 folded into qi)
//   row_sum    = 1024 + 0.5*sum_j tanh   ->  out = fmaf(t, h, h), h = 0.5/row_sum
// Block = 1024 threads, IT=8 i-rows, grid (256, 8). Thread t owns j = {2t,2t+1}
// held as plain floats in registers. Per i: 2 broadcast LDS.128 of qi, four
// independent scalar FMA chains (depth 4). No packed-math ALU overhead.
// Output stored with __stcs (evict-first: write-once data, keep L2 for g_rot).
// ---------------------------------------------------------------------------
__global__ __launch_bounds__(1024, 1) void attn_kernel(float* __restrict__ out)
{
    const int b    = blockIdx.y;
    const int i0   = blockIdx.x * IT;
    const int tid  = threadIdx.x;
    const int warp = tid >> 5;
    const int lane = tid & 31;

    __shared__ float s_q[IT * NQ];     // 0.5 * qi rows, 64 floats
    __shared__ float s_part[IT][32];
    __shared__ float s_h[IT];

    if (tid < IT * NQ)
        s_q[tid] = 0.5f * g_rot[((size_t)b * LEN + i0) * NQ + tid];

    // this thread's 2 j-rows (64B contiguous), kept as 4 float4 registers
    const float4* rj = reinterpret_cast<const float4*>(
        &g_rot[((size_t)b * LEN + tid * 2) * NQ]);
    const float4 vA0 = rj[0], vA1 = rj[1], vB0 = rj[2], vB1 = rj[3];

    __syncthreads();

    float tA[IT], tB[IT], a[IT];
    const float4* sq4 = reinterpret_cast<const float4*>(s_q);

#pragma unroll
    for (int i = 0; i < IT; i++) {
        // 2 broadcast LDS.128 fetch the 8 qi values for row i
        const float4 q0 = sq4[i * 2 + 0];
        const float4 q1 = sq4[i * 2 + 1];
        // four independent depth-4 FMA chains
        float sA0 = vA0.x * q0.x;
        float sA1 = vA1.x * q1.x;
        float sB0 = vB0.x * q0.x;
        float sB1 = vB1.x * q1.x;
        sA0 = fmaf(vA0.y, q0.y, sA0);  sA1 = fmaf(vA1.y, q1.y, sA1);
        sB0 = fmaf(vB0.y, q0.y, sB0);  sB1 = fmaf(vB1.y, q1.y, sB1);
        sA0 = fmaf(vA0.z, q0.z, sA0);  sA1 = fmaf(vA1.z, q1.z, sA1);
        sB0 = fmaf(vB0.z, q0.z, sB0);  sB1 = fmaf(vB1.z, q1.z, sB1);
        sA0 = fmaf(vA0.w, q0.w, sA0);  sA1 = fmaf(vA1.w, q1.w, sA1);
        sB0 = fmaf(vB0.w, q0.w, sB0);  sB1 = fmaf(vB1.w, q1.w, sB1);
        tA[i] = tanh_fast(sA0 + sA1);
        tB[i] = tanh_fast(sB0 + sB1);
        a[i] = tA[i] + tB[i];
    }

    // swap-butterfly warp reduce of 8 row partials: stages 4,2,1 then 8,16.
    // After: every lane holds this warp's partial for row (lane & 7).
#pragma unroll
    for (int off = 4; off >= 1; off >>= 1) {
#pragma unroll
        for (int t = 0; t < 4; t++) {
            if (t < off) {
                const bool hi = (lane & off) != 0;
                const float give = hi ? a[t] : a[t + off];
                const float keep = hi ? a[t + off] : a[t];
                a[t] = keep + __shfl_xor_sync(0xffffffffu, give, off);
            }
        }
    }
    a[0] += __shfl_xor_sync(0xffffffffu, a[0], 8);
    a[0] += __shfl_xor_sync(0xffffffffu, a[0], 16);

    if (lane < IT)
        s_part[lane][warp] = a[0];

    __syncthreads();

    // second level: warp i (<8) reduces row i's 32 warp-partials
    if (warp < IT) {
        float p = s_part[warp][lane];
#pragma unroll
        for (int off = 16; off > 0; off >>= 1)
            p += __shfl_xor_sync(0xffffffffu, p, off);
        if (lane == 0)
            s_h[warp] = __fdividef(0.5f, fmaf(0.5f, p, 1024.0f));
    }
    __syncthreads();

    float2* obase = reinterpret_cast<float2*>(
        out + ((size_t)(b * LEN + i0)) * LEN) + tid;
#pragma unroll
    for (int i = 0; i < IT; i++) {
        const float h = s_h[i];
        float2 o;
        o.x = fmaf(tA[i], h, h);
        o.y = fmaf(tB[i], h, h);
        __stcs(obase, o);                 // evict-first streaming store
        obase += LEN / 2;
    }
}

extern "C" void kernel_launch(void* const* d_in, const int* in_sizes, int n_in,
                              void* d_out, int out_size)
{
    const float* x        = (const float*)d_in[0];   // (8, 2048, 512)
    const float* rotation = (const float*)d_in[1];   // (512, 8)
    float* out = (float*)d_out;                      // (8, 2048, 2048)

    rot_kernel<<<1024, 256>>>(x, rotation);

    dim3 grid(LEN / IT, BATCH);                      // (256, 8)
    attn_kernel<<<grid, 1024>>>(out);
}